// round 3
// baseline (speedup 1.0000x reference)
#include <cuda_runtime.h>
#include <cuda_fp16.h>
#include <cstdint>

// ============================================================================
// BitLinear: y = (clip(LN(x) * 128/gamma, +-(128-.01)) @ w) * beta*gamma/128
//   x: [4,2048,4096] f32 -> M=8192, K=4096;  w: [4096,4096] f32 (+-1)
// Base sm_100 target: NO tcgen05 (family-specific). Use mma.sync HMMA
// (sm_80 ISA) + ldmatrix + cp.async 4-stage pipeline.
// Dequant scale beta*gamma/128 folded into A during preprocessing.
// ============================================================================

constexpr int M_TOT = 8192;
constexpr int N_TOT = 4096;
constexpr int K_TOT = 4096;

// Scratch (allocations forbidden; device globals are the sanctioned path)
__device__ __half g_A[(size_t)M_TOT * K_TOT];   // 64 MB, LN+quant output, K-major
__device__ __half g_Bt[(size_t)N_TOT * K_TOT];  // 32 MB, w transposed, K-major

// ---------------------------------------------------------------------------
// PTX helpers (all base-target legal: sm_80+)
// ---------------------------------------------------------------------------
__device__ __forceinline__ uint32_t smem_u32(const void* p) {
    uint32_t a;
    asm("{ .reg .u64 t; cvta.to.shared.u64 t, %1; cvt.u32.u64 %0, t; }"
        : "=r"(a) : "l"(p));
    return a;
}

#define CP_ASYNC16(smem, gptr) \
    asm volatile("cp.async.cg.shared.global [%0], [%1], 16;" \
                 :: "r"(smem), "l"(gptr) : "memory")
#define CP_COMMIT() asm volatile("cp.async.commit_group;" ::: "memory")
#define CP_WAIT(n)  asm volatile("cp.async.wait_group %0;" :: "n"(n) : "memory")

#define LDSM_X4(r0, r1, r2, r3, addr) \
    asm volatile("ldmatrix.sync.aligned.m8n8.x4.shared.b16 {%0,%1,%2,%3}, [%4];" \
                 : "=r"(r0), "=r"(r1), "=r"(r2), "=r"(r3) : "r"(addr))

#define MMA16816(c0, c1, c2, c3, a0, a1, a2, a3, b0, b1) \
    asm volatile("mma.sync.aligned.m16n8k16.row.col.f32.f16.f16.f32 " \
                 "{%0,%1,%2,%3}, {%4,%5,%6,%7}, {%8,%9}, {%0,%1,%2,%3};" \
                 : "+f"(c0), "+f"(c1), "+f"(c2), "+f"(c3) \
                 : "r"(a0), "r"(a1), "r"(a2), "r"(a3), "r"(b0), "r"(b1))

// ---------------------------------------------------------------------------
// Kernel 1: fused LayerNorm + absmax-quant + clip + scale-fold -> fp16 A
// one block per row; 256 threads, 16 elems/thread
// ---------------------------------------------------------------------------
__global__ void __launch_bounds__(256) lnq_kernel(
    const float* __restrict__ x, const float* __restrict__ lng,
    const float* __restrict__ lnb, const float* __restrict__ bet,
    const float* __restrict__ gam)
{
    int row = blockIdx.x;
    int tid = threadIdx.x;
    const float4* xr = reinterpret_cast<const float4*>(x + (size_t)row * K_TOT);

    float4 v[4];
    float s = 0.f, s2 = 0.f;
#pragma unroll
    for (int i = 0; i < 4; i++) {
        v[i] = xr[tid + i * 256];
        s  += v[i].x + v[i].y + v[i].z + v[i].w;
        s2 += v[i].x * v[i].x + v[i].y * v[i].y + v[i].z * v[i].z + v[i].w * v[i].w;
    }
#pragma unroll
    for (int o = 16; o; o >>= 1) {
        s  += __shfl_xor_sync(0xffffffffu, s, o);
        s2 += __shfl_xor_sync(0xffffffffu, s2, o);
    }
    __shared__ float rs[8], rs2[8];
    if ((tid & 31) == 0) { rs[tid >> 5] = s; rs2[tid >> 5] = s2; }
    __syncthreads();
    s = 0.f; s2 = 0.f;
#pragma unroll
    for (int i = 0; i < 8; i++) { s += rs[i]; s2 += rs2[i]; }

    const float inv_k = 1.0f / (float)K_TOT;
    float mu   = s * inv_k;
    float var  = s2 * inv_k - mu * mu;
    float rstd = rsqrtf(var + 1e-5f);
    float g  = *gam;
    float qs = 128.0f / g;                       // absmax quant scale
    float os = (*bet) * g * (1.0f / 128.0f);     // folded dequant scale
    const float lo = -128.0f + 0.01f;
    const float hi =  128.0f - 0.01f;

    const float4* lg4 = reinterpret_cast<const float4*>(lng);
    const float4* lb4 = reinterpret_cast<const float4*>(lnb);
    uint2* dst = reinterpret_cast<uint2*>(g_A + (size_t)row * K_TOT);

#pragma unroll
    for (int i = 0; i < 4; i++) {
        int idx = tid + i * 256;
        float4 gv = lg4[idx], bv = lb4[idx];
        float e0 = ((v[i].x - mu) * rstd * gv.x + bv.x) * qs;
        float e1 = ((v[i].y - mu) * rstd * gv.y + bv.y) * qs;
        float e2 = ((v[i].z - mu) * rstd * gv.z + bv.z) * qs;
        float e3 = ((v[i].w - mu) * rstd * gv.w + bv.w) * qs;
        e0 = fminf(fmaxf(e0, lo), hi) * os;
        e1 = fminf(fmaxf(e1, lo), hi) * os;
        e2 = fminf(fmaxf(e2, lo), hi) * os;
        e3 = fminf(fmaxf(e3, lo), hi) * os;
        __half2 h0 = __floats2half2_rn(e0, e1);
        __half2 h1 = __floats2half2_rn(e2, e3);
        uint2 u;
        u.x = *reinterpret_cast<uint32_t*>(&h0);
        u.y = *reinterpret_cast<uint32_t*>(&h1);
        dst[idx] = u;
    }
}

// ---------------------------------------------------------------------------
// Kernel 2: w[k][n] f32 -> g_Bt[n][k] fp16 (32x32 tiled transpose)
// ---------------------------------------------------------------------------
__global__ void __launch_bounds__(256) wconv_kernel(const float* __restrict__ w)
{
    __shared__ float t[32][33];
    int k0 = blockIdx.x * 32, n0 = blockIdx.y * 32;
    int tx = threadIdx.x, ty = threadIdx.y;        // tx: 0..31, ty: 0..7
    int tid = ty * 32 + tx;
#pragma unroll
    for (int j = 0; j < 32; j += 8)
        t[ty + j][tx] = w[(size_t)(k0 + ty + j) * N_TOT + n0 + tx];
    __syncthreads();
    // 512 (n, k-pair) cells; bijective over idx = tid + pass*256
#pragma unroll
    for (int pass = 0; pass < 2; pass++) {
        int idx = tid + pass * 256;
        int n  = idx >> 4;          // 0..31
        int kp = idx & 15;          // 0..15 -> k = 2*kp
        __half2 h = __floats2half2_rn(t[2 * kp][n], t[2 * kp + 1][n]);
        *reinterpret_cast<__half2*>(&g_Bt[(size_t)(n0 + n) * K_TOT + k0 + 2 * kp]) = h;
    }
}

// ---------------------------------------------------------------------------
// Kernel 3: HMMA GEMM  out[M,N] = A[M,K] @ Bt[N,K]^T
//   CTA 128x256, BK=32, 8 warps (2m x 4n) of 64x64, 4-stage cp.async
//   SMEM rows padded to 40 halves (80 B): conflict-free ldmatrix (gcd(5,8)=1)
// ---------------------------------------------------------------------------
constexpr int BM = 128, BN = 256, BK = 32, STAGES = 4;
constexpr int KT = K_TOT / BK;                     // 128
constexpr int ROW_B = 80;                          // padded row bytes (40 halves)
constexpr int A_STAGE = BM * ROW_B;                // 10240
constexpr int B_STAGE = BN * ROW_B;                // 20480
constexpr int STAGE_B = A_STAGE + B_STAGE;         // 30720
constexpr int SMEM_GEMM = STAGES * STAGE_B;        // 122880

__global__ void __launch_bounds__(256) gemm_kernel(float* __restrict__ out)
{
    extern __shared__ char smem[];
    uint32_t sb = smem_u32(smem);
    int tid = threadIdx.x;
    int wid = tid >> 5;
    int lid = tid & 31;
    int n0 = blockIdx.x * BN;
    int m0 = blockIdx.y * BM;

    int wm = wid & 1;              // 0..1  -> m offset wm*64
    int wn = wid >> 1;             // 0..3  -> n offset wn*64

    // ---- global load indices (2 A-chunks + 4 B-chunks of 16B per thread) ----
    // A: 512 chunks: row = idx>>2 (0..127), ch = idx&3
    // B: 1024 chunks: row = idx>>2 (0..255), ch = idx&3
    const __half* gA = g_A + (size_t)m0 * K_TOT;
    const __half* gB = g_Bt + (size_t)n0 * K_TOT;

    // ---- per-lane ldmatrix base offsets (within a stage) ----
    // A x4 tile: row = wm*64 + mt*16 + (l&15), kcol_half = kh*16 + (l>>4)*8
    uint32_t a_off = (uint32_t)(wm * 64 + (lid & 15)) * ROW_B + (uint32_t)(lid >> 4) * 16;
    // B x4 tile: row = wn*64 + nb*16 + (l&7) + ((l&16)?8:0), kcol_half = kh*16 + ((l&8)?8:0)
    uint32_t b_off = (uint32_t)(wn * 64 + (lid & 7) + ((lid & 16) ? 8 : 0)) * ROW_B
                   + (uint32_t)((lid & 8) ? 16 : 0);

    float acc[4][8][4];
#pragma unroll
    for (int i = 0; i < 4; i++)
#pragma unroll
        for (int j = 0; j < 8; j++)
#pragma unroll
            for (int q = 0; q < 4; q++) acc[i][j][q] = 0.f;

    // ---- pipeline prologue: fill stages 0..2 ----
#pragma unroll
    for (int s = 0; s < STAGES - 1; s++) {
        uint32_t st = sb + s * STAGE_B;
#pragma unroll
        for (int r = 0; r < 2; r++) {
            int idx = tid + r * 256;
            CP_ASYNC16(st + (uint32_t)(idx >> 2) * ROW_B + (uint32_t)(idx & 3) * 16,
                       gA + (size_t)(idx >> 2) * K_TOT + s * BK + (idx & 3) * 8);
        }
#pragma unroll
        for (int r = 0; r < 4; r++) {
            int idx = tid + r * 256;
            CP_ASYNC16(st + A_STAGE + (uint32_t)(idx >> 2) * ROW_B + (uint32_t)(idx & 3) * 16,
                       gB + (size_t)(idx >> 2) * K_TOT + s * BK + (idx & 3) * 8);
        }
        CP_COMMIT();
    }

    // ---- main loop ----
    for (int kt = 0; kt < KT; kt++) {
        CP_WAIT(2);
        __syncthreads();

        // issue loads for stage kt+3 (overwrites stage used at kt-1; safe post-sync)
        if (kt + STAGES - 1 < KT) {
            uint32_t st = sb + ((kt + STAGES - 1) & 3) * STAGE_B;
            int kofs = (kt + STAGES - 1) * BK;
#pragma unroll
            for (int r = 0; r < 2; r++) {
                int idx = tid + r * 256;
                CP_ASYNC16(st + (uint32_t)(idx >> 2) * ROW_B + (uint32_t)(idx & 3) * 16,
                           gA + (size_t)(idx >> 2) * K_TOT + kofs + (idx & 3) * 8);
            }
#pragma unroll
            for (int r = 0; r < 4; r++) {
                int idx = tid + r * 256;
                CP_ASYNC16(st + A_STAGE + (uint32_t)(idx >> 2) * ROW_B + (uint32_t)(idx & 3) * 16,
                           gB + (size_t)(idx >> 2) * K_TOT + kofs + (idx & 3) * 8);
            }
        }
        CP_COMMIT();

        // compute on stage kt&3
        uint32_t sa = sb + (kt & 3) * STAGE_B + a_off;
        uint32_t sB = sb + (kt & 3) * STAGE_B + A_STAGE + b_off;
#pragma unroll
        for (int kh = 0; kh < 2; kh++) {          // two k16 halves of BK=32
            uint32_t af[4][4], bf[4][4];
#pragma unroll
            for (int mt = 0; mt < 4; mt++)
                LDSM_X4(af[mt][0], af[mt][1], af[mt][2], af[mt][3],
                        sa + (uint32_t)mt * (16 * ROW_B) + (uint32_t)kh * 32);
#pragma unroll
            for (int nb = 0; nb < 4; nb++)
                LDSM_X4(bf[nb][0], bf[nb][1], bf[nb][2], bf[nb][3],
                        sB + (uint32_t)nb * (16 * ROW_B) + (uint32_t)kh * 32);
#pragma unroll
            for (int mt = 0; mt < 4; mt++) {
#pragma unroll
                for (int nb = 0; nb < 4; nb++) {
                    // nb covers two n8 tiles: regs (0,1) = n tile 2*nb, (2,3) = 2*nb+1
                    MMA16816(acc[mt][2 * nb][0], acc[mt][2 * nb][1],
                             acc[mt][2 * nb][2], acc[mt][2 * nb][3],
                             af[mt][0], af[mt][1], af[mt][2], af[mt][3],
                             bf[nb][0], bf[nb][1]);
                    MMA16816(acc[mt][2 * nb + 1][0], acc[mt][2 * nb + 1][1],
                             acc[mt][2 * nb + 1][2], acc[mt][2 * nb + 1][3],
                             af[mt][0], af[mt][1], af[mt][2], af[mt][3],
                             bf[nb][2], bf[nb][3]);
                }
            }
        }
    }

    // ---- epilogue: direct stores, v2 per (tile, row-half) ----
    int r_base = m0 + wm * 64 + (lid >> 2);
    int c_base = n0 + wn * 64 + 2 * (lid & 3);
#pragma unroll
    for (int mt = 0; mt < 4; mt++) {
#pragma unroll
        for (int nt = 0; nt < 8; nt++) {
            int r = r_base + mt * 16;
            int c = c_base + nt * 8;
            float* p0 = out + (size_t)r * N_TOT + c;
            float* p1 = out + (size_t)(r + 8) * N_TOT + c;
            p0[0] = acc[mt][nt][0]; p0[1] = acc[mt][nt][1];
            p1[0] = acc[mt][nt][2]; p1[1] = acc[mt][nt][3];
        }
    }
}

// ---------------------------------------------------------------------------
// launch
// ---------------------------------------------------------------------------
extern "C" void kernel_launch(void* const* d_in, const int* in_sizes, int n_in,
                              void* d_out, int out_size)
{
    const float* x     = (const float*)d_in[0];
    const float* w     = (const float*)d_in[1];
    const float* lng   = (const float*)d_in[2];
    const float* lnb   = (const float*)d_in[3];
    const float* beta  = (const float*)d_in[4];
    const float* gamma = (const float*)d_in[5];
    float* out = (float*)d_out;

    lnq_kernel<<<M_TOT, 256>>>(x, lng, lnb, beta, gamma);
    wconv_kernel<<<dim3(K_TOT / 32, N_TOT / 32), dim3(32, 8)>>>(w);

    static bool attr_set = false;
    if (!attr_set) {
        cudaFuncSetAttribute(gemm_kernel,
                             cudaFuncAttributeMaxDynamicSharedMemorySize, SMEM_GEMM);
        attr_set = true;
    }
    gemm_kernel<<<dim3(N_TOT / BN, M_TOT / BM), 256, SMEM_GEMM>>>(out);
}

// round 4
// speedup vs baseline: 1.1886x; 1.1886x over previous
#include <cuda_runtime.h>
#include <cuda_fp16.h>
#include <cstdint>

// ============================================================================
// BitLinear: y = (clip(LN(x) * 128/gamma, +-(128-.01)) @ w) * beta*gamma/128
//   x: [4,2048,4096] f32 -> M=8192, K=4096;  w: [4096,4096] f32 (+-1)
// Base sm_100 target (no tcgen05). mma.sync HMMA + ldmatrix + cp.async.
// R4: BK=64 / 4 stages / fragment double-buffering; prep kernels merged.
// ============================================================================

constexpr int M_TOT = 8192;
constexpr int N_TOT = 4096;
constexpr int K_TOT = 4096;

__device__ __half g_A[(size_t)M_TOT * K_TOT];   // 64 MB
__device__ __half g_Bt[(size_t)N_TOT * K_TOT];  // 32 MB

// ---------------------------------------------------------------------------
__device__ __forceinline__ uint32_t smem_u32(const void* p) {
    uint32_t a;
    asm("{ .reg .u64 t; cvta.to.shared.u64 t, %1; cvt.u32.u64 %0, t; }"
        : "=r"(a) : "l"(p));
    return a;
}

#define CP_ASYNC16(smem, gptr) \
    asm volatile("cp.async.cg.shared.global [%0], [%1], 16;" \
                 :: "r"(smem), "l"(gptr) : "memory")
#define CP_COMMIT() asm volatile("cp.async.commit_group;" ::: "memory")
#define CP_WAIT(n)  asm volatile("cp.async.wait_group %0;" :: "n"(n) : "memory")

#define LDSM_X4(r0, r1, r2, r3, addr) \
    asm volatile("ldmatrix.sync.aligned.m8n8.x4.shared.b16 {%0,%1,%2,%3}, [%4];" \
                 : "=r"(r0), "=r"(r1), "=r"(r2), "=r"(r3) : "r"(addr))

#define MMA16816(c0, c1, c2, c3, a0, a1, a2, a3, b0, b1) \
    asm volatile("mma.sync.aligned.m16n8k16.row.col.f32.f16.f16.f32 " \
                 "{%0,%1,%2,%3}, {%4,%5,%6,%7}, {%8,%9}, {%0,%1,%2,%3};" \
                 : "+f"(c0), "+f"(c1), "+f"(c2), "+f"(c3) \
                 : "r"(a0), "r"(a1), "r"(a2), "r"(a3), "r"(b0), "r"(b1))

// ---------------------------------------------------------------------------
// Kernel 1 (merged): blocks [0, 8192) = LN+quant rows; [8192, 24576) = wconv
// ---------------------------------------------------------------------------
__global__ void __launch_bounds__(256) prep_kernel(
    const float* __restrict__ x, const float* __restrict__ w,
    const float* __restrict__ lng, const float* __restrict__ lnb,
    const float* __restrict__ bet, const float* __restrict__ gam)
{
    int tid = threadIdx.x;
    if (blockIdx.x < 8192) {
        // ---- LayerNorm + quant + clip + scale-fold -> g_A (fp16) ----
        int row = blockIdx.x;
        const float4* xr = reinterpret_cast<const float4*>(x + (size_t)row * K_TOT);

        float4 v[4];
        float s = 0.f, s2 = 0.f;
#pragma unroll
        for (int i = 0; i < 4; i++) {
            v[i] = xr[tid + i * 256];
            s  += v[i].x + v[i].y + v[i].z + v[i].w;
            s2 += v[i].x * v[i].x + v[i].y * v[i].y + v[i].z * v[i].z + v[i].w * v[i].w;
        }
#pragma unroll
        for (int o = 16; o; o >>= 1) {
            s  += __shfl_xor_sync(0xffffffffu, s, o);
            s2 += __shfl_xor_sync(0xffffffffu, s2, o);
        }
        __shared__ float rs[8], rs2[8];
        if ((tid & 31) == 0) { rs[tid >> 5] = s; rs2[tid >> 5] = s2; }
        __syncthreads();
        s = 0.f; s2 = 0.f;
#pragma unroll
        for (int i = 0; i < 8; i++) { s += rs[i]; s2 += rs2[i]; }

        const float inv_k = 1.0f / (float)K_TOT;
        float mu   = s * inv_k;
        float var  = s2 * inv_k - mu * mu;
        float rstd = rsqrtf(var + 1e-5f);
        float g  = *gam;
        float qs = 128.0f / g;
        float os = (*bet) * g * (1.0f / 128.0f);
        const float lo = -128.0f + 0.01f;
        const float hi =  128.0f - 0.01f;

        const float4* lg4 = reinterpret_cast<const float4*>(lng);
        const float4* lb4 = reinterpret_cast<const float4*>(lnb);
        uint2* dst = reinterpret_cast<uint2*>(g_A + (size_t)row * K_TOT);

#pragma unroll
        for (int i = 0; i < 4; i++) {
            int idx = tid + i * 256;
            float4 gv = lg4[idx], bv = lb4[idx];
            float e0 = ((v[i].x - mu) * rstd * gv.x + bv.x) * qs;
            float e1 = ((v[i].y - mu) * rstd * gv.y + bv.y) * qs;
            float e2 = ((v[i].z - mu) * rstd * gv.z + bv.z) * qs;
            float e3 = ((v[i].w - mu) * rstd * gv.w + bv.w) * qs;
            e0 = fminf(fmaxf(e0, lo), hi) * os;
            e1 = fminf(fmaxf(e1, lo), hi) * os;
            e2 = fminf(fmaxf(e2, lo), hi) * os;
            e3 = fminf(fmaxf(e3, lo), hi) * os;
            __half2 h0 = __floats2half2_rn(e0, e1);
            __half2 h1 = __floats2half2_rn(e2, e3);
            uint2 u;
            u.x = *reinterpret_cast<uint32_t*>(&h0);
            u.y = *reinterpret_cast<uint32_t*>(&h1);
            dst[idx] = u;
        }
    } else {
        // ---- w[k][n] f32 -> g_Bt[n][k] fp16 (32x32 transpose) ----
        __shared__ float t[32][33];
        int b2 = blockIdx.x - 8192;
        int k0 = (b2 & 127) * 32, n0 = (b2 >> 7) * 32;
        int tx = tid & 31, ty = tid >> 5;   // 32 x 8
#pragma unroll
        for (int j = 0; j < 32; j += 8)
            t[ty + j][tx] = w[(size_t)(k0 + ty + j) * N_TOT + n0 + tx];
        __syncthreads();
#pragma unroll
        for (int pass = 0; pass < 2; pass++) {
            int idx = tid + pass * 256;
            int n  = idx >> 4;          // 0..31
            int kp = idx & 15;          // k = 2*kp
            __half2 h = __floats2half2_rn(t[2 * kp][n], t[2 * kp + 1][n]);
            *reinterpret_cast<__half2*>(&g_Bt[(size_t)(n0 + n) * K_TOT + k0 + 2 * kp]) = h;
        }
    }
}

// ---------------------------------------------------------------------------
// Kernel 2: HMMA GEMM  out[M,N] = A[M,K] @ Bt[N,K]^T
//   CTA 128x256, BK=64, 4 stages, 8 warps (2m x 4n) of 64x64
//   SMEM rows 144 B (72 halves): 144 = 36 banks -> 4r mod 32 distinct over
//   8 rows -> conflict-free ldmatrix.  4 stages = 221,184 B smem.
// ---------------------------------------------------------------------------
constexpr int BM = 128, BN = 256, BK = 64, STAGES = 4;
constexpr int KT = K_TOT / BK;                     // 64
constexpr int ROW_B = 144;                         // padded row bytes
constexpr int A_STAGE = BM * ROW_B;                // 18432
constexpr int B_STAGE = BN * ROW_B;                // 36864
constexpr int STAGE_B = A_STAGE + B_STAGE;         // 55296
constexpr int SMEM_GEMM = STAGES * STAGE_B;        // 221184

__global__ void __launch_bounds__(256) gemm_kernel(float* __restrict__ out)
{
    extern __shared__ char smem[];
    uint32_t sb = smem_u32(smem);
    int tid = threadIdx.x;
    int wid = tid >> 5;
    int lid = tid & 31;
    int n0 = blockIdx.x * BN;
    int m0 = blockIdx.y * BM;

    int wm = wid & 1;              // m offset wm*64
    int wn = wid >> 1;             // n offset wn*64

    const __half* gA = g_A + (size_t)m0 * K_TOT;
    const __half* gB = g_Bt + (size_t)n0 * K_TOT;

    // per-lane ldmatrix base offsets (within a stage)
    uint32_t a_off = (uint32_t)(wm * 64 + (lid & 15)) * ROW_B + (uint32_t)(lid >> 4) * 16;
    uint32_t b_off = (uint32_t)(wn * 64 + (lid & 7) + ((lid & 16) ? 8 : 0)) * ROW_B
                   + (uint32_t)((lid & 8) ? 16 : 0);

    float acc[4][8][4];
#pragma unroll
    for (int i = 0; i < 4; i++)
#pragma unroll
        for (int j = 0; j < 8; j++)
#pragma unroll
            for (int q = 0; q < 4; q++) acc[i][j][q] = 0.f;

    // global->smem loader: A 1024 chunks (4/thread), B 2048 chunks (8/thread)
    // chunk: row = idx>>3, ch = idx&7  (8 x 16B per 128B row)
#define LOAD_STAGE(stg, kofs)                                                        \
    do {                                                                             \
        uint32_t _st = sb + (uint32_t)(stg) * STAGE_B;                               \
        _Pragma("unroll")                                                            \
        for (int r = 0; r < 4; r++) {                                                \
            int idx = tid + r * 256;                                                 \
            CP_ASYNC16(_st + (uint32_t)(idx >> 3) * ROW_B + (uint32_t)(idx & 7) * 16,\
                       gA + (size_t)(idx >> 3) * K_TOT + (kofs) + (idx & 7) * 8);    \
        }                                                                            \
        _Pragma("unroll")                                                            \
        for (int r = 0; r < 8; r++) {                                                \
            int idx = tid + r * 256;                                                 \
            CP_ASYNC16(_st + A_STAGE + (uint32_t)(idx >> 3) * ROW_B                  \
                           + (uint32_t)(idx & 7) * 16,                               \
                       gB + (size_t)(idx >> 3) * K_TOT + (kofs) + (idx & 7) * 8);    \
        }                                                                            \
        CP_COMMIT();                                                                 \
    } while (0)

#define LOAD_FRAGS(buf, sa, sB, kh)                                                  \
    do {                                                                             \
        _Pragma("unroll")                                                            \
        for (int mt = 0; mt < 4; mt++)                                               \
            LDSM_X4(af[buf][mt][0], af[buf][mt][1], af[buf][mt][2], af[buf][mt][3],  \
                    (sa) + (uint32_t)mt * (16 * ROW_B) + (uint32_t)(kh) * 32);       \
        _Pragma("unroll")                                                            \
        for (int nb = 0; nb < 4; nb++)                                               \
            LDSM_X4(bf[buf][nb][0], bf[buf][nb][1], bf[buf][nb][2], bf[buf][nb][3],  \
                    (sB) + (uint32_t)nb * (16 * ROW_B) + (uint32_t)(kh) * 32);       \
    } while (0)

    // prologue: fill stages 0..2
#pragma unroll
    for (int s = 0; s < STAGES - 1; s++) LOAD_STAGE(s, s * BK);

    int s_comp = 0;
    int s_load = STAGES - 1;

    for (int kt = 0; kt < KT; kt++) {
        CP_WAIT(2);
        __syncthreads();

        if (kt + STAGES - 1 < KT) {
            LOAD_STAGE(s_load, (kt + STAGES - 1) * BK);
        } else {
            CP_COMMIT();   // keep group count aligned with CP_WAIT(2)
        }
        if (++s_load == STAGES) s_load = 0;

        uint32_t sa = sb + (uint32_t)s_comp * STAGE_B + a_off;
        uint32_t sB = sb + (uint32_t)s_comp * STAGE_B + A_STAGE + b_off;
        if (++s_comp == STAGES) s_comp = 0;

        uint32_t af[2][4][4], bf[2][4][4];
        LOAD_FRAGS(0, sa, sB, 0);
#pragma unroll
        for (int kh = 0; kh < 4; kh++) {
            int cur = kh & 1;
            if (kh < 3) LOAD_FRAGS(cur ^ 1, sa, sB, kh + 1);
#pragma unroll
            for (int mt = 0; mt < 4; mt++) {
#pragma unroll
                for (int nb = 0; nb < 4; nb++) {
                    MMA16816(acc[mt][2 * nb][0], acc[mt][2 * nb][1],
                             acc[mt][2 * nb][2], acc[mt][2 * nb][3],
                             af[cur][mt][0], af[cur][mt][1], af[cur][mt][2], af[cur][mt][3],
                             bf[cur][nb][0], bf[cur][nb][1]);
                    MMA16816(acc[mt][2 * nb + 1][0], acc[mt][2 * nb + 1][1],
                             acc[mt][2 * nb + 1][2], acc[mt][2 * nb + 1][3],
                             af[cur][mt][0], af[cur][mt][1], af[cur][mt][2], af[cur][mt][3],
                             bf[cur][nb][2], bf[cur][nb][3]);
                }
            }
        }
    }

    // epilogue: direct v2 stores
    int r_base = m0 + wm * 64 + (lid >> 2);
    int c_base = n0 + wn * 64 + 2 * (lid & 3);
#pragma unroll
    for (int mt = 0; mt < 4; mt++) {
#pragma unroll
        for (int nt = 0; nt < 8; nt++) {
            int r = r_base + mt * 16;
            int c = c_base + nt * 8;
            float* p0 = out + (size_t)r * N_TOT + c;
            float* p1 = out + (size_t)(r + 8) * N_TOT + c;
            p0[0] = acc[mt][nt][0]; p0[1] = acc[mt][nt][1];
            p1[0] = acc[mt][nt][2]; p1[1] = acc[mt][nt][3];
        }
    }
}

// ---------------------------------------------------------------------------
extern "C" void kernel_launch(void* const* d_in, const int* in_sizes, int n_in,
                              void* d_out, int out_size)
{
    const float* x     = (const float*)d_in[0];
    const float* w     = (const float*)d_in[1];
    const float* lng   = (const float*)d_in[2];
    const float* lnb   = (const float*)d_in[3];
    const float* beta  = (const float*)d_in[4];
    const float* gamma = (const float*)d_in[5];
    float* out = (float*)d_out;

    prep_kernel<<<8192 + 16384, 256>>>(x, w, lng, lnb, beta, gamma);

    cudaFuncSetAttribute(gemm_kernel,
                         cudaFuncAttributeMaxDynamicSharedMemorySize, SMEM_GEMM);
    gemm_kernel<<<dim3(N_TOT / BN, M_TOT / BM), 256, SMEM_GEMM>>>(out);
}

// round 5
// speedup vs baseline: 1.2147x; 1.0220x over previous
#include <cuda_runtime.h>
#include <cuda_fp16.h>
#include <cstdint>

// ============================================================================
// BitLinear: y = (clip(LN(x) * 128/gamma, +-(128-.01)) @ w) * beta*gamma/128
//   x: [4,2048,4096] f32 -> M=8192, K=4096;  w: [4096,4096] f32 (+-1)
// Base sm_100 target (no tcgen05). mma.sync HMMA + ldmatrix + cp.async.
// R5: cross-kt fragment prefetch (kt-boundary ldsm latency off the critical
//     path), CP_WAIT(1); prep merged as before.
// ============================================================================

constexpr int M_TOT = 8192;
constexpr int N_TOT = 4096;
constexpr int K_TOT = 4096;

__device__ __half g_A[(size_t)M_TOT * K_TOT];   // 64 MB
__device__ __half g_Bt[(size_t)N_TOT * K_TOT];  // 32 MB

// ---------------------------------------------------------------------------
__device__ __forceinline__ uint32_t smem_u32(const void* p) {
    uint32_t a;
    asm("{ .reg .u64 t; cvta.to.shared.u64 t, %1; cvt.u32.u64 %0, t; }"
        : "=r"(a) : "l"(p));
    return a;
}

#define CP_ASYNC16(smem, gptr) \
    asm volatile("cp.async.cg.shared.global [%0], [%1], 16;" \
                 :: "r"(smem), "l"(gptr) : "memory")
#define CP_COMMIT() asm volatile("cp.async.commit_group;" ::: "memory")
#define CP_WAIT(n)  asm volatile("cp.async.wait_group %0;" :: "n"(n) : "memory")

#define LDSM_X4(r0, r1, r2, r3, addr) \
    asm volatile("ldmatrix.sync.aligned.m8n8.x4.shared.b16 {%0,%1,%2,%3}, [%4];" \
                 : "=r"(r0), "=r"(r1), "=r"(r2), "=r"(r3) : "r"(addr))

#define MMA16816(c0, c1, c2, c3, a0, a1, a2, a3, b0, b1) \
    asm volatile("mma.sync.aligned.m16n8k16.row.col.f32.f16.f16.f32 " \
                 "{%0,%1,%2,%3}, {%4,%5,%6,%7}, {%8,%9}, {%0,%1,%2,%3};" \
                 : "+f"(c0), "+f"(c1), "+f"(c2), "+f"(c3) \
                 : "r"(a0), "r"(a1), "r"(a2), "r"(a3), "r"(b0), "r"(b1))

// ---------------------------------------------------------------------------
// Kernel 1 (merged): blocks [0, 8192) = LN+quant rows; [8192, 24576) = wconv
// ---------------------------------------------------------------------------
__global__ void __launch_bounds__(256) prep_kernel(
    const float* __restrict__ x, const float* __restrict__ w,
    const float* __restrict__ lng, const float* __restrict__ lnb,
    const float* __restrict__ bet, const float* __restrict__ gam)
{
    int tid = threadIdx.x;
    if (blockIdx.x < 8192) {
        int row = blockIdx.x;
        const float4* xr = reinterpret_cast<const float4*>(x + (size_t)row * K_TOT);

        float4 v[4];
        float s = 0.f, s2 = 0.f;
#pragma unroll
        for (int i = 0; i < 4; i++) {
            v[i] = xr[tid + i * 256];
            s  += v[i].x + v[i].y + v[i].z + v[i].w;
            s2 += v[i].x * v[i].x + v[i].y * v[i].y + v[i].z * v[i].z + v[i].w * v[i].w;
        }
#pragma unroll
        for (int o = 16; o; o >>= 1) {
            s  += __shfl_xor_sync(0xffffffffu, s, o);
            s2 += __shfl_xor_sync(0xffffffffu, s2, o);
        }
        __shared__ float rs[8], rs2[8];
        if ((tid & 31) == 0) { rs[tid >> 5] = s; rs2[tid >> 5] = s2; }
        __syncthreads();
        s = 0.f; s2 = 0.f;
#pragma unroll
        for (int i = 0; i < 8; i++) { s += rs[i]; s2 += rs2[i]; }

        const float inv_k = 1.0f / (float)K_TOT;
        float mu   = s * inv_k;
        float var  = s2 * inv_k - mu * mu;
        float rstd = rsqrtf(var + 1e-5f);
        float g  = *gam;
        float qs = 128.0f / g;
        float os = (*bet) * g * (1.0f / 128.0f);
        const float lo = -128.0f + 0.01f;
        const float hi =  128.0f - 0.01f;

        const float4* lg4 = reinterpret_cast<const float4*>(lng);
        const float4* lb4 = reinterpret_cast<const float4*>(lnb);
        uint2* dst = reinterpret_cast<uint2*>(g_A + (size_t)row * K_TOT);

#pragma unroll
        for (int i = 0; i < 4; i++) {
            int idx = tid + i * 256;
            float4 gv = lg4[idx], bv = lb4[idx];
            float e0 = ((v[i].x - mu) * rstd * gv.x + bv.x) * qs;
            float e1 = ((v[i].y - mu) * rstd * gv.y + bv.y) * qs;
            float e2 = ((v[i].z - mu) * rstd * gv.z + bv.z) * qs;
            float e3 = ((v[i].w - mu) * rstd * gv.w + bv.w) * qs;
            e0 = fminf(fmaxf(e0, lo), hi) * os;
            e1 = fminf(fmaxf(e1, lo), hi) * os;
            e2 = fminf(fmaxf(e2, lo), hi) * os;
            e3 = fminf(fmaxf(e3, lo), hi) * os;
            __half2 h0 = __floats2half2_rn(e0, e1);
            __half2 h1 = __floats2half2_rn(e2, e3);
            uint2 u;
            u.x = *reinterpret_cast<uint32_t*>(&h0);
            u.y = *reinterpret_cast<uint32_t*>(&h1);
            dst[idx] = u;
        }
    } else {
        __shared__ float t[32][33];
        int b2 = blockIdx.x - 8192;
        int k0 = (b2 & 127) * 32, n0 = (b2 >> 7) * 32;
        int tx = tid & 31, ty = tid >> 5;
#pragma unroll
        for (int j = 0; j < 32; j += 8)
            t[ty + j][tx] = w[(size_t)(k0 + ty + j) * N_TOT + n0 + tx];
        __syncthreads();
#pragma unroll
        for (int pass = 0; pass < 2; pass++) {
            int idx = tid + pass * 256;
            int n  = idx >> 4;
            int kp = idx & 15;
            __half2 h = __floats2half2_rn(t[2 * kp][n], t[2 * kp + 1][n]);
            *reinterpret_cast<__half2*>(&g_Bt[(size_t)(n0 + n) * K_TOT + k0 + 2 * kp]) = h;
        }
    }
}

// ---------------------------------------------------------------------------
// Kernel 2: HMMA GEMM  out[M,N] = A[M,K] @ Bt[N,K]^T
//   CTA 128x256, BK=64, 4 stages, 8 warps (2m x 4n) of 64x64.
//   Cross-kt fragment prefetch: kh0 frags of kt+1 loaded during kh3 of kt.
// ---------------------------------------------------------------------------
constexpr int BM = 128, BN = 256, BK = 64, STAGES = 4;
constexpr int KT = K_TOT / BK;                     // 64
constexpr int ROW_B = 144;                         // padded row bytes
constexpr int A_STAGE = BM * ROW_B;                // 18432
constexpr int B_STAGE = BN * ROW_B;                // 36864
constexpr int STAGE_B = A_STAGE + B_STAGE;         // 55296
constexpr int SMEM_GEMM = STAGES * STAGE_B;        // 221184

__global__ void __launch_bounds__(256) gemm_kernel(float* __restrict__ out)
{
    extern __shared__ char smem[];
    uint32_t sb = smem_u32(smem);
    int tid = threadIdx.x;
    int wid = tid >> 5;
    int lid = tid & 31;
    int n0 = blockIdx.x * BN;
    int m0 = blockIdx.y * BM;

    int wm = wid & 1;
    int wn = wid >> 1;

    const __half* gA = g_A + (size_t)m0 * K_TOT;
    const __half* gB = g_Bt + (size_t)n0 * K_TOT;

    uint32_t a_off = (uint32_t)(wm * 64 + (lid & 15)) * ROW_B + (uint32_t)(lid >> 4) * 16;
    uint32_t b_off = (uint32_t)(wn * 64 + (lid & 7) + ((lid & 16) ? 8 : 0)) * ROW_B
                   + (uint32_t)((lid & 8) ? 16 : 0);

    float acc[4][8][4];
#pragma unroll
    for (int i = 0; i < 4; i++)
#pragma unroll
        for (int j = 0; j < 8; j++)
#pragma unroll
            for (int q = 0; q < 4; q++) acc[i][j][q] = 0.f;

#define LOAD_STAGE(stg, kofs)                                                        \
    do {                                                                             \
        uint32_t _st = sb + (uint32_t)(stg) * STAGE_B;                               \
        _Pragma("unroll")                                                            \
        for (int r = 0; r < 4; r++) {                                                \
            int idx = tid + r * 256;                                                 \
            CP_ASYNC16(_st + (uint32_t)(idx >> 3) * ROW_B + (uint32_t)(idx & 7) * 16,\
                       gA + (size_t)(idx >> 3) * K_TOT + (kofs) + (idx & 7) * 8);    \
        }                                                                            \
        _Pragma("unroll")                                                            \
        for (int r = 0; r < 8; r++) {                                                \
            int idx = tid + r * 256;                                                 \
            CP_ASYNC16(_st + A_STAGE + (uint32_t)(idx >> 3) * ROW_B                  \
                           + (uint32_t)(idx & 7) * 16,                               \
                       gB + (size_t)(idx >> 3) * K_TOT + (kofs) + (idx & 7) * 8);    \
        }                                                                            \
        CP_COMMIT();                                                                 \
    } while (0)

#define LOAD_FRAGS(buf, sa, sB, kh)                                                  \
    do {                                                                             \
        _Pragma("unroll")                                                            \
        for (int mt = 0; mt < 4; mt++)                                               \
            LDSM_X4(af[buf][mt][0], af[buf][mt][1], af[buf][mt][2], af[buf][mt][3],  \
                    (sa) + (uint32_t)mt * (16 * ROW_B) + (uint32_t)(kh) * 32);       \
        _Pragma("unroll")                                                            \
        for (int nb = 0; nb < 4; nb++)                                               \
            LDSM_X4(bf[buf][nb][0], bf[buf][nb][1], bf[buf][nb][2], bf[buf][nb][3],  \
                    (sB) + (uint32_t)nb * (16 * ROW_B) + (uint32_t)(kh) * 32);       \
    } while (0)

    // prologue: fill stages 0..2
#pragma unroll
    for (int s = 0; s < STAGES - 1; s++) LOAD_STAGE(s, s * BK);

    uint32_t af[2][4][4], bf[2][4][4];

    // preload frags for kt=0, kh=0 (stage 0 guaranteed by WAIT(2)+sync)
    CP_WAIT(2);
    __syncthreads();
    LOAD_FRAGS(0, sb + a_off, sb + A_STAGE + b_off, 0);

    int s_load = STAGES - 1;

    for (int kt = 0; kt < KT; kt++) {
        // stages kt AND kt+1 guaranteed resident after this wait
        CP_WAIT(1);
        __syncthreads();

        if (kt + STAGES - 1 < KT) {
            LOAD_STAGE(s_load, (kt + STAGES - 1) * BK);
        } else {
            CP_COMMIT();   // keep group ledger aligned with CP_WAIT(1)
        }
        if (++s_load == STAGES) s_load = 0;

        uint32_t sa_cur = sb + (uint32_t)(kt & 3) * STAGE_B + a_off;
        uint32_t sB_cur = sb + (uint32_t)(kt & 3) * STAGE_B + A_STAGE + b_off;
        // next-kt stage (for cross-boundary prefetch at kh==3); for kt==KT-1
        // this reads stale-but-valid smem that is never consumed.
        uint32_t sa_nxt = sb + (uint32_t)((kt + 1) & 3) * STAGE_B + a_off;
        uint32_t sB_nxt = sb + (uint32_t)((kt + 1) & 3) * STAGE_B + A_STAGE + b_off;

#pragma unroll
        for (int kh = 0; kh < 4; kh++) {
            int cur = kh & 1;
            if (kh < 3) {
                LOAD_FRAGS(cur ^ 1, sa_cur, sB_cur, kh + 1);
            } else {
                LOAD_FRAGS(cur ^ 1, sa_nxt, sB_nxt, 0);  // kh3 -> buf0 = next kt kh0
            }
#pragma unroll
            for (int mt = 0; mt < 4; mt++) {
#pragma unroll
                for (int nb = 0; nb < 4; nb++) {
                    MMA16816(acc[mt][2 * nb][0], acc[mt][2 * nb][1],
                             acc[mt][2 * nb][2], acc[mt][2 * nb][3],
                             af[cur][mt][0], af[cur][mt][1], af[cur][mt][2], af[cur][mt][3],
                             bf[cur][nb][0], bf[cur][nb][1]);
                    MMA16816(acc[mt][2 * nb + 1][0], acc[mt][2 * nb + 1][1],
                             acc[mt][2 * nb + 1][2], acc[mt][2 * nb + 1][3],
                             af[cur][mt][0], af[cur][mt][1], af[cur][mt][2], af[cur][mt][3],
                             bf[cur][nb][2], bf[cur][nb][3]);
                }
            }
        }
    }

    // epilogue: direct v2 stores
    int r_base = m0 + wm * 64 + (lid >> 2);
    int c_base = n0 + wn * 64 + 2 * (lid & 3);
#pragma unroll
    for (int mt = 0; mt < 4; mt++) {
#pragma unroll
        for (int nt = 0; nt < 8; nt++) {
            int r = r_base + mt * 16;
            int c = c_base + nt * 8;
            float* p0 = out + (size_t)r * N_TOT + c;
            float* p1 = out + (size_t)(r + 8) * N_TOT + c;
            p0[0] = acc[mt][nt][0]; p0[1] = acc[mt][nt][1];
            p1[0] = acc[mt][nt][2]; p1[1] = acc[mt][nt][3];
        }
    }
}

// ---------------------------------------------------------------------------
extern "C" void kernel_launch(void* const* d_in, const int* in_sizes, int n_in,
                              void* d_out, int out_size)
{
    const float* x     = (const float*)d_in[0];
    const float* w     = (const float*)d_in[1];
    const float* lng   = (const float*)d_in[2];
    const float* lnb   = (const float*)d_in[3];
    const float* beta  = (const float*)d_in[4];
    const float* gamma = (const float*)d_in[5];
    float* out = (float*)d_out;

    prep_kernel<<<8192 + 16384, 256>>>(x, w, lng, lnb, beta, gamma);

    cudaFuncSetAttribute(gemm_kernel,
                         cudaFuncAttributeMaxDynamicSharedMemorySize, SMEM_GEMM);
    gemm_kernel<<<dim3(N_TOT / BN, M_TOT / BM), 256, SMEM_GEMM>>>(out);
}

// round 6
// speedup vs baseline: 1.2206x; 1.0049x over previous
#include <cuda_runtime.h>
#include <cuda_fp16.h>
#include <cstdint>

// ============================================================================
// BitLinear: y = (clip(LN(x) * 128/gamma, +-(128-.01)) @ w) * beta*gamma/128
//   x: [4,2048,4096] f32 -> M=8192, K=4096;  w: [4096,4096] f32 (+-1)
// Base sm_100 target (no tcgen05). mma.sync HMMA + ldmatrix + cp.async.
// R6: 512 threads / 16 warps per CTA (4 warps/SMSP) to deepen the warp pool;
//     warp tile 32x64; same 128x256 CTA tile, BK=64, 4 stages.
// ============================================================================

constexpr int M_TOT = 8192;
constexpr int N_TOT = 4096;
constexpr int K_TOT = 4096;

__device__ __half g_A[(size_t)M_TOT * K_TOT];   // 64 MB
__device__ __half g_Bt[(size_t)N_TOT * K_TOT];  // 32 MB

// ---------------------------------------------------------------------------
__device__ __forceinline__ uint32_t smem_u32(const void* p) {
    uint32_t a;
    asm("{ .reg .u64 t; cvta.to.shared.u64 t, %1; cvt.u32.u64 %0, t; }"
        : "=r"(a) : "l"(p));
    return a;
}

#define CP_ASYNC16(smem, gptr) \
    asm volatile("cp.async.cg.shared.global [%0], [%1], 16;" \
                 :: "r"(smem), "l"(gptr) : "memory")
#define CP_COMMIT() asm volatile("cp.async.commit_group;" ::: "memory")
#define CP_WAIT(n)  asm volatile("cp.async.wait_group %0;" :: "n"(n) : "memory")

#define LDSM_X4(r0, r1, r2, r3, addr) \
    asm volatile("ldmatrix.sync.aligned.m8n8.x4.shared.b16 {%0,%1,%2,%3}, [%4];" \
                 : "=r"(r0), "=r"(r1), "=r"(r2), "=r"(r3) : "r"(addr))

#define MMA16816(c0, c1, c2, c3, a0, a1, a2, a3, b0, b1) \
    asm volatile("mma.sync.aligned.m16n8k16.row.col.f32.f16.f16.f32 " \
                 "{%0,%1,%2,%3}, {%4,%5,%6,%7}, {%8,%9}, {%0,%1,%2,%3};" \
                 : "+f"(c0), "+f"(c1), "+f"(c2), "+f"(c3) \
                 : "r"(a0), "r"(a1), "r"(a2), "r"(a3), "r"(b0), "r"(b1))

// ---------------------------------------------------------------------------
// Kernel 1 (merged): blocks [0, 8192) = LN+quant rows; [8192, 24576) = wconv
// ---------------------------------------------------------------------------
__global__ void __launch_bounds__(256) prep_kernel(
    const float* __restrict__ x, const float* __restrict__ w,
    const float* __restrict__ lng, const float* __restrict__ lnb,
    const float* __restrict__ bet, const float* __restrict__ gam)
{
    int tid = threadIdx.x;
    if (blockIdx.x < 8192) {
        int row = blockIdx.x;
        const float4* xr = reinterpret_cast<const float4*>(x + (size_t)row * K_TOT);

        float4 v[4];
        float s = 0.f, s2 = 0.f;
#pragma unroll
        for (int i = 0; i < 4; i++) {
            v[i] = xr[tid + i * 256];
            s  += v[i].x + v[i].y + v[i].z + v[i].w;
            s2 += v[i].x * v[i].x + v[i].y * v[i].y + v[i].z * v[i].z + v[i].w * v[i].w;
        }
#pragma unroll
        for (int o = 16; o; o >>= 1) {
            s  += __shfl_xor_sync(0xffffffffu, s, o);
            s2 += __shfl_xor_sync(0xffffffffu, s2, o);
        }
        __shared__ float rs[8], rs2[8];
        if ((tid & 31) == 0) { rs[tid >> 5] = s; rs2[tid >> 5] = s2; }
        __syncthreads();
        s = 0.f; s2 = 0.f;
#pragma unroll
        for (int i = 0; i < 8; i++) { s += rs[i]; s2 += rs2[i]; }

        const float inv_k = 1.0f / (float)K_TOT;
        float mu   = s * inv_k;
        float var  = s2 * inv_k - mu * mu;
        float rstd = rsqrtf(var + 1e-5f);
        float g  = *gam;
        float qs = 128.0f / g;
        float os = (*bet) * g * (1.0f / 128.0f);
        const float lo = -128.0f + 0.01f;
        const float hi =  128.0f - 0.01f;

        const float4* lg4 = reinterpret_cast<const float4*>(lng);
        const float4* lb4 = reinterpret_cast<const float4*>(lnb);
        uint2* dst = reinterpret_cast<uint2*>(g_A + (size_t)row * K_TOT);

#pragma unroll
        for (int i = 0; i < 4; i++) {
            int idx = tid + i * 256;
            float4 gv = lg4[idx], bv = lb4[idx];
            float e0 = ((v[i].x - mu) * rstd * gv.x + bv.x) * qs;
            float e1 = ((v[i].y - mu) * rstd * gv.y + bv.y) * qs;
            float e2 = ((v[i].z - mu) * rstd * gv.z + bv.z) * qs;
            float e3 = ((v[i].w - mu) * rstd * gv.w + bv.w) * qs;
            e0 = fminf(fmaxf(e0, lo), hi) * os;
            e1 = fminf(fmaxf(e1, lo), hi) * os;
            e2 = fminf(fmaxf(e2, lo), hi) * os;
            e3 = fminf(fmaxf(e3, lo), hi) * os;
            __half2 h0 = __floats2half2_rn(e0, e1);
            __half2 h1 = __floats2half2_rn(e2, e3);
            uint2 u;
            u.x = *reinterpret_cast<uint32_t*>(&h0);
            u.y = *reinterpret_cast<uint32_t*>(&h1);
            dst[idx] = u;
        }
    } else {
        __shared__ float t[32][33];
        int b2 = blockIdx.x - 8192;
        int k0 = (b2 & 127) * 32, n0 = (b2 >> 7) * 32;
        int tx = tid & 31, ty = tid >> 5;
#pragma unroll
        for (int j = 0; j < 32; j += 8)
            t[ty + j][tx] = w[(size_t)(k0 + ty + j) * N_TOT + n0 + tx];
        __syncthreads();
#pragma unroll
        for (int pass = 0; pass < 2; pass++) {
            int idx = tid + pass * 256;
            int n  = idx >> 4;
            int kp = idx & 15;
            __half2 h = __floats2half2_rn(t[2 * kp][n], t[2 * kp + 1][n]);
            *reinterpret_cast<__half2*>(&g_Bt[(size_t)(n0 + n) * K_TOT + k0 + 2 * kp]) = h;
        }
    }
}

// ---------------------------------------------------------------------------
// Kernel 2: HMMA GEMM  out[M,N] = A[M,K] @ Bt[N,K]^T
//   CTA 128x256, BK=64, 4 stages, 512 threads / 16 warps (4m x 4n) of 32x64.
//   SMEM rows 144 B -> conflict-free ldmatrix. Cross-kt fragment prefetch.
// ---------------------------------------------------------------------------
constexpr int BM = 128, BN = 256, BK = 64, STAGES = 4;
constexpr int KT = K_TOT / BK;                     // 64
constexpr int ROW_B = 144;                         // padded row bytes
constexpr int A_STAGE = BM * ROW_B;                // 18432
constexpr int B_STAGE = BN * ROW_B;                // 36864
constexpr int STAGE_B = A_STAGE + B_STAGE;         // 55296
constexpr int SMEM_GEMM = STAGES * STAGE_B;        // 221184
constexpr int NT = 512;

__global__ void __launch_bounds__(NT, 1) gemm_kernel(float* __restrict__ out)
{
    extern __shared__ char smem[];
    uint32_t sb = smem_u32(smem);
    int tid = threadIdx.x;
    int wid = tid >> 5;
    int lid = tid & 31;
    int n0 = blockIdx.x * BN;
    int m0 = blockIdx.y * BM;

    int wm = wid & 3;              // m offset wm*32
    int wn = wid >> 2;             // n offset wn*64

    const __half* gA = g_A + (size_t)m0 * K_TOT;
    const __half* gB = g_Bt + (size_t)n0 * K_TOT;

    // per-lane ldmatrix base offsets (within a stage)
    uint32_t a_off = (uint32_t)(wm * 32 + (lid & 15)) * ROW_B + (uint32_t)(lid >> 4) * 16;
    uint32_t b_off = (uint32_t)(wn * 64 + (lid & 7) + ((lid & 16) ? 8 : 0)) * ROW_B
                   + (uint32_t)((lid & 8) ? 16 : 0);

    float acc[2][8][4];
#pragma unroll
    for (int i = 0; i < 2; i++)
#pragma unroll
        for (int j = 0; j < 8; j++)
#pragma unroll
            for (int q = 0; q < 4; q++) acc[i][j][q] = 0.f;

    // A: 1024 16B chunks (2/thread), B: 2048 (4/thread); row = idx>>3, ch = idx&7
#define LOAD_STAGE(stg, kofs)                                                        \
    do {                                                                             \
        uint32_t _st = sb + (uint32_t)(stg) * STAGE_B;                               \
        _Pragma("unroll")                                                            \
        for (int r = 0; r < 2; r++) {                                                \
            int idx = tid + r * NT;                                                  \
            CP_ASYNC16(_st + (uint32_t)(idx >> 3) * ROW_B + (uint32_t)(idx & 7) * 16,\
                       gA + (size_t)(idx >> 3) * K_TOT + (kofs) + (idx & 7) * 8);    \
        }                                                                            \
        _Pragma("unroll")                                                            \
        for (int r = 0; r < 4; r++) {                                                \
            int idx = tid + r * NT;                                                  \
            CP_ASYNC16(_st + A_STAGE + (uint32_t)(idx >> 3) * ROW_B                  \
                           + (uint32_t)(idx & 7) * 16,                               \
                       gB + (size_t)(idx >> 3) * K_TOT + (kofs) + (idx & 7) * 8);    \
        }                                                                            \
        CP_COMMIT();                                                                 \
    } while (0)

#define LOAD_FRAGS(buf, sa, sB, kh)                                                  \
    do {                                                                             \
        _Pragma("unroll")                                                            \
        for (int mt = 0; mt < 2; mt++)                                               \
            LDSM_X4(af[buf][mt][0], af[buf][mt][1], af[buf][mt][2], af[buf][mt][3],  \
                    (sa) + (uint32_t)mt * (16 * ROW_B) + (uint32_t)(kh) * 32);       \
        _Pragma("unroll")                                                            \
        for (int nb = 0; nb < 4; nb++)                                               \
            LDSM_X4(bf[buf][nb][0], bf[buf][nb][1], bf[buf][nb][2], bf[buf][nb][3],  \
                    (sB) + (uint32_t)nb * (16 * ROW_B) + (uint32_t)(kh) * 32);       \
    } while (0)

    // prologue: fill stages 0..2
#pragma unroll
    for (int s = 0; s < STAGES - 1; s++) LOAD_STAGE(s, s * BK);

    uint32_t af[2][2][4], bf[2][4][4];

    // preload frags for kt=0, kh=0 (stage 0 guaranteed by WAIT(2)+sync)
    CP_WAIT(2);
    __syncthreads();
    LOAD_FRAGS(0, sb + a_off, sb + A_STAGE + b_off, 0);

    int s_load = STAGES - 1;

    for (int kt = 0; kt < KT; kt++) {
        // stages kt AND kt+1 guaranteed resident after this wait
        CP_WAIT(1);
        __syncthreads();

        if (kt + STAGES - 1 < KT) {
            LOAD_STAGE(s_load, (kt + STAGES - 1) * BK);
        } else {
            CP_COMMIT();   // keep group ledger aligned with CP_WAIT(1)
        }
        if (++s_load == STAGES) s_load = 0;

        uint32_t sa_cur = sb + (uint32_t)(kt & 3) * STAGE_B + a_off;
        uint32_t sB_cur = sb + (uint32_t)(kt & 3) * STAGE_B + A_STAGE + b_off;
        uint32_t sa_nxt = sb + (uint32_t)((kt + 1) & 3) * STAGE_B + a_off;
        uint32_t sB_nxt = sb + (uint32_t)((kt + 1) & 3) * STAGE_B + A_STAGE + b_off;

#pragma unroll
        for (int kh = 0; kh < 4; kh++) {
            int cur = kh & 1;
            if (kh < 3) {
                LOAD_FRAGS(cur ^ 1, sa_cur, sB_cur, kh + 1);
            } else {
                LOAD_FRAGS(cur ^ 1, sa_nxt, sB_nxt, 0);  // next kt, kh0
            }
#pragma unroll
            for (int mt = 0; mt < 2; mt++) {
#pragma unroll
                for (int nb = 0; nb < 4; nb++) {
                    MMA16816(acc[mt][2 * nb][0], acc[mt][2 * nb][1],
                             acc[mt][2 * nb][2], acc[mt][2 * nb][3],
                             af[cur][mt][0], af[cur][mt][1], af[cur][mt][2], af[cur][mt][3],
                             bf[cur][nb][0], bf[cur][nb][1]);
                    MMA16816(acc[mt][2 * nb + 1][0], acc[mt][2 * nb + 1][1],
                             acc[mt][2 * nb + 1][2], acc[mt][2 * nb + 1][3],
                             af[cur][mt][0], af[cur][mt][1], af[cur][mt][2], af[cur][mt][3],
                             bf[cur][nb][2], bf[cur][nb][3]);
                }
            }
        }
    }

    // epilogue: direct v2 stores
    int r_base = m0 + wm * 32 + (lid >> 2);
    int c_base = n0 + wn * 64 + 2 * (lid & 3);
#pragma unroll
    for (int mt = 0; mt < 2; mt++) {
#pragma unroll
        for (int nt = 0; nt < 8; nt++) {
            int r = r_base + mt * 16;
            int c = c_base + nt * 8;
            float* p0 = out + (size_t)r * N_TOT + c;
            float* p1 = out + (size_t)(r + 8) * N_TOT + c;
            p0[0] = acc[mt][nt][0]; p0[1] = acc[mt][nt][1];
            p1[0] = acc[mt][nt][2]; p1[1] = acc[mt][nt][3];
        }
    }
}

// ---------------------------------------------------------------------------
extern "C" void kernel_launch(void* const* d_in, const int* in_sizes, int n_in,
                              void* d_out, int out_size)
{
    const float* x     = (const float*)d_in[0];
    const float* w     = (const float*)d_in[1];
    const float* lng   = (const float*)d_in[2];
    const float* lnb   = (const float*)d_in[3];
    const float* beta  = (const float*)d_in[4];
    const float* gamma = (const float*)d_in[5];
    float* out = (float*)d_out;

    prep_kernel<<<8192 + 16384, 256>>>(x, w, lng, lnb, beta, gamma);

    cudaFuncSetAttribute(gemm_kernel,
                         cudaFuncAttributeMaxDynamicSharedMemorySize, SMEM_GEMM);
    gemm_kernel<<<dim3(N_TOT / BN, M_TOT / BM), NT, SMEM_GEMM>>>(out);
}